// round 9
// baseline (speedup 1.0000x reference)
#include <cuda_runtime.h>
#include <cuda_fp16.h>
#include <cstdint>

// EdgeNetwork as warp-level HMMA GEMM (mma.sync.m16n8k16):
//   msg[e,i] = sum_{K=0..271} C[e,K] * W[K,i],  K = k*16+j
//   C[e,K]   = b'[e,k] * A[nb_e, j],  b' = [b[e], 1.0]  (k=16 row folds bias)
//   W[k*16+j, i] = Kmat[k, i*16+j]  (k<16),  bias[i*16+j] (k=16)
// Warp = 2 interleaved 16-edge tiles (4 independent HMMA streams per k-step).

#define NW 8                  // warps per CTA
#define EPC (NW * 2 * 16)     // 256 edges per CTA

__device__ __forceinline__ void red_add_v2(float* addr, float x, float y) {
    asm volatile("red.global.add.v2.f32 [%0], {%1,%2};"
                 :: "l"(addr), "f"(x), "f"(y) : "memory");
}

__device__ __forceinline__ unsigned hmul2u(__half2 a, __half2 b) {
    __half2 r = __hmul2(a, b);
    return *reinterpret_cast<unsigned*>(&r);
}

__device__ __forceinline__ void mma16816(float& d0, float& d1, float& d2,
                                         float& d3, unsigned a0, unsigned a1,
                                         unsigned a2, unsigned a3,
                                         unsigned b0, unsigned b1) {
    asm volatile(
        "mma.sync.aligned.m16n8k16.row.col.f32.f16.f16.f32 "
        "{%0,%1,%2,%3}, {%4,%5,%6,%7}, {%8,%9}, {%0,%1,%2,%3};"
        : "+f"(d0), "+f"(d1), "+f"(d2), "+f"(d3)
        : "r"(a0), "r"(a1), "r"(a2), "r"(a3), "r"(b0), "r"(b1));
}

__global__ void __launch_bounds__(NW * 32)
edge_hmma(const float* __restrict__ bond,
          const int* __restrict__ pairs,
          const float* __restrict__ A,
          const float* __restrict__ Kmat,
          const float* __restrict__ bias,
          float* __restrict__ out,
          int n_edges) {
    __shared__ __half Wsm[16 * 280];            // row stride 280 halfs
    __shared__ __half2 bbuf[NW][2][16][8];      // [warp][tile][s][rowpair] 8KB

    const int tid = threadIdx.x;
    const int lane = tid & 31;
    const int w = tid >> 5;
    const int g = lane >> 2;      // fragment row group (0..7)
    const int t = lane & 3;       // fragment quad (0..3)

    // build W image directly from Kmat/bias (L2-resident, ~17KB reads)
    for (int idx = tid; idx < 16 * 272; idx += NW * 32) {
        const int i = idx / 272;          // output index (n)
        const int K = idx % 272;          // K position
        const int k = K >> 4;
        const int j = K & 15;
        const float v = (k < 16) ? Kmat[k * 256 + i * 16 + j]
                                 : bias[i * 16 + j];
        Wsm[i * 280 + K] = __float2half_rn(v);
    }
    __syncthreads();

    const int warp_base = blockIdx.x * EPC + w * 32;

    // ---- stage bond rows for both tiles ----
    #pragma unroll
    for (int tl = 0; tl < 2; ++tl) {
        const int ebase = warp_base + tl * 16;
        const int et = lane >> 1;
        const int hcol = lane & 1;          // 0 -> s 0..7, 1 -> s 8..15
        const int esrc = min(ebase + et, n_edges - 1);
        const float4* b4 = reinterpret_cast<const float4*>(bond)
                         + (size_t)esrc * 4 + hcol * 2;
        const float4 f0 = b4[0];
        const float4 f1 = b4[1];
        float bf[8] = {f0.x, f0.y, f0.z, f0.w, f1.x, f1.y, f1.z, f1.w};
        __half* bb = reinterpret_cast<__half*>(bbuf[w][tl]);
        const int r = et & 7;
        const int hi = et >> 3;
        #pragma unroll
        for (int c = 0; c < 8; ++c) {
            const int s = hcol * 8 + c;
            bb[(s * 8 + r) * 2 + hi] = __float2half_rn(bf[c]);
        }
    }
    __syncwarp();

    // ---- per-thread edges / A fragments for both tiles ----
    int2 p0[2], p1[2];
    __half2 hal0[2], hah0[2], hal1[2], hah1[2];
    #pragma unroll
    for (int tl = 0; tl < 2; ++tl) {
        const int ebase = warp_base + tl * 16;
        const int e0 = min(ebase + g, n_edges - 1);
        const int e1 = min(ebase + g + 8, n_edges - 1);
        p0[tl] = reinterpret_cast<const int2*>(pairs)[e0];
        p1[tl] = reinterpret_cast<const int2*>(pairs)[e1];
        const float* A0 = A + (size_t)p0[tl].y * 16;
        const float* A1 = A + (size_t)p1[tl].y * 16;
        const float2 al0 = *reinterpret_cast<const float2*>(A0 + 2 * t);
        const float2 ah0 = *reinterpret_cast<const float2*>(A0 + 8 + 2 * t);
        const float2 al1 = *reinterpret_cast<const float2*>(A1 + 2 * t);
        const float2 ah1 = *reinterpret_cast<const float2*>(A1 + 8 + 2 * t);
        hal0[tl] = __floats2half2_rn(al0.x, al0.y);
        hah0[tl] = __floats2half2_rn(ah0.x, ah0.y);
        hal1[tl] = __floats2half2_rn(al1.x, al1.y);
        hah1[tl] = __floats2half2_rn(ah1.x, ah1.y);
    }

    float d[2][8];
    #pragma unroll
    for (int tl = 0; tl < 2; ++tl)
        #pragma unroll
        for (int q = 0; q < 8; ++q) d[tl][q] = 0.f;

    #pragma unroll
    for (int s = 0; s < 17; ++s) {
        // B fragments: shared by both tiles (depend only on s, g, t)
        const __half* Wr0 = Wsm + g * 280 + s * 16 + t * 2;
        const __half* Wr1 = Wsm + (g + 8) * 280 + s * 16 + t * 2;
        const unsigned b00 = *reinterpret_cast<const unsigned*>(Wr0);
        const unsigned b01 = *reinterpret_cast<const unsigned*>(Wr0 + 8);
        const unsigned b10 = *reinterpret_cast<const unsigned*>(Wr1);
        const unsigned b11 = *reinterpret_cast<const unsigned*>(Wr1 + 8);

        #pragma unroll
        for (int tl = 0; tl < 2; ++tl) {
            __half2 bl, bh;
            if (s < 16) {
                const __half2 b2 = bbuf[w][tl][s][g];  // (b[e0][s], b[e1][s])
                bl = __half2half2(__low2half(b2));
                bh = __half2half2(__high2half(b2));
            } else {
                bl = __floats2half2_rn(1.f, 1.f);      // bias row
                bh = bl;
            }
            const unsigned a0 = hmul2u(bl, hal0[tl]);
            const unsigned a1 = hmul2u(bh, hal1[tl]);
            const unsigned a2 = hmul2u(bl, hah0[tl]);
            const unsigned a3 = hmul2u(bh, hah1[tl]);

            mma16816(d[tl][0], d[tl][1], d[tl][2], d[tl][3],
                     a0, a1, a2, a3, b00, b01);
            mma16816(d[tl][4], d[tl][5], d[tl][6], d[tl][7],
                     a0, a1, a2, a3, b10, b11);
        }
    }

    // ---- epilogue ----
    #pragma unroll
    for (int tl = 0; tl < 2; ++tl) {
        const int ebase = warp_base + tl * 16;
        const int e0 = ebase + g;
        const int e1 = ebase + g + 8;
        if (e0 < n_edges) {
            float* o = out + (size_t)p0[tl].x * 16;
            red_add_v2(o + 2 * t, d[tl][0], d[tl][1]);
            red_add_v2(o + 8 + 2 * t, d[tl][4], d[tl][5]);
        }
        if (e1 < n_edges) {
            float* o = out + (size_t)p1[tl].x * 16;
            red_add_v2(o + 2 * t, d[tl][2], d[tl][3]);
            red_add_v2(o + 8 + 2 * t, d[tl][6], d[tl][7]);
        }
    }
}

extern "C" void kernel_launch(void* const* d_in, const int* in_sizes, int n_in,
                              void* d_out, int out_size) {
    const float* A     = (const float*)d_in[0];  // atom_features [n_atoms,16]
    const float* bond  = (const float*)d_in[1];  // bond_features [n_edges,16]
    const int*   pairs = (const int*)  d_in[2];  // pair_indices  [n_edges,2]
    const float* Kmat  = (const float*)d_in[3];  // kernel [16,256]
    const float* bias  = (const float*)d_in[4];  // bias [256]
    float* out = (float*)d_out;                  // [n_atoms,16]

    const int n_edges = in_sizes[2] / 2;

    cudaMemsetAsync(out, 0, (size_t)out_size * sizeof(float), 0);

    const int blocks = (n_edges + EPC - 1) / EPC;
    edge_hmma<<<blocks, NW * 32>>>(bond, pairs, A, Kmat, bias, out, n_edges);
}

// round 10
// speedup vs baseline: 1.1533x; 1.1533x over previous
#include <cuda_runtime.h>
#include <cuda_fp16.h>
#include <cstdint>

// EdgeNetwork as warp-level HMMA GEMM (mma.sync.m16n8k16):
//   msg[e,i] = sum_{K=0..271} C[e,K] * W[K,i],  K = k*16+j
//   C[e,K]   = b'[e,k] * A[nb_e, j],  b' = [b[e], 1.0]  (k=16 row folds bias)
//   W[k*16+j, i] = Kmat[k, i*16+j]  (k<16),  bias[i*16+j] (k=16)
// Warp processes 2 pairs of interleaved 16-edge tiles (4 independent HMMA
// streams per k-step); W image prebuilt once (verbatim smem copy, no ALU).

#define NW 8                  // warps per CTA
#define NPAIR 2               // tile-pairs per warp
#define EPC (NW * NPAIR * 32) // 512 edges per CTA

// prebuilt fp16 W image, padded row stride 280 halfs (bank-conflict-free LDS)
__device__ __half g_Wimg[16 * 280];

__device__ __forceinline__ void red_add_v2(float* addr, float x, float y) {
    asm volatile("red.global.add.v2.f32 [%0], {%1,%2};"
                 :: "l"(addr), "f"(x), "f"(y) : "memory");
}

__device__ __forceinline__ unsigned hmul2u(__half2 a, __half2 b) {
    __half2 r = __hmul2(a, b);
    return *reinterpret_cast<unsigned*>(&r);
}

__device__ __forceinline__ void mma16816(float& d0, float& d1, float& d2,
                                         float& d3, unsigned a0, unsigned a1,
                                         unsigned a2, unsigned a3,
                                         unsigned b0, unsigned b1) {
    asm volatile(
        "mma.sync.aligned.m16n8k16.row.col.f32.f16.f16.f32 "
        "{%0,%1,%2,%3}, {%4,%5,%6,%7}, {%8,%9}, {%0,%1,%2,%3};"
        : "+f"(d0), "+f"(d1), "+f"(d2), "+f"(d3)
        : "r"(a0), "r"(a1), "r"(a2), "r"(a3), "r"(b0), "r"(b1));
}

// ---------------- build W image (tiny, once per launch) ---------------------
__global__ void build_w(const float* __restrict__ Kmat,
                        const float* __restrict__ bias) {
    const int tid = threadIdx.x;  // 256
    for (int idx = tid; idx < 16 * 272; idx += 256) {
        const int i = idx / 272;          // output index (n)
        const int K = idx % 272;          // K position
        const int k = K >> 4;
        const int j = K & 15;
        const float v = (k < 16) ? Kmat[k * 256 + i * 16 + j]
                                 : bias[i * 16 + j];
        g_Wimg[i * 280 + K] = __float2half_rn(v);
    }
}

// ---------------- main edge kernel -------------------------------------------
__global__ void __launch_bounds__(NW * 32)
edge_hmma(const float* __restrict__ bond,
          const int* __restrict__ pairs,
          const float* __restrict__ A,
          float* __restrict__ out,
          int n_edges) {
    __shared__ __half Wsm[16 * 280];            // 8960 B
    __shared__ __half2 bbuf[NW][2][16][8];      // [warp][tile-in-pair][s][rowpair]

    const int tid = threadIdx.x;
    const int lane = tid & 31;
    const int w = tid >> 5;
    const int g = lane >> 2;      // fragment row group (0..7)
    const int t = lane & 3;       // fragment quad (0..3)

    // stage W image (verbatim, 560 uint4 — no ALU)
    {
        const uint4* src = reinterpret_cast<const uint4*>(g_Wimg);
        uint4* dst = reinterpret_cast<uint4*>(Wsm);
        for (int i = tid; i < 560; i += NW * 32) dst[i] = src[i];
    }
    __syncthreads();

    const int warp_base = blockIdx.x * EPC + w * (NPAIR * 32);

    for (int pr_i = 0; pr_i < NPAIR; ++pr_i) {
        const int pbase = warp_base + pr_i * 32;

        // ---- stage bond rows for both tiles of this pair ----
        #pragma unroll
        for (int tl = 0; tl < 2; ++tl) {
            const int ebase = pbase + tl * 16;
            const int et = lane >> 1;
            const int hcol = lane & 1;          // 0 -> s 0..7, 1 -> s 8..15
            const int esrc = min(ebase + et, n_edges - 1);
            const float4* b4 = reinterpret_cast<const float4*>(bond)
                             + (size_t)esrc * 4 + hcol * 2;
            const float4 f0 = b4[0];
            const float4 f1 = b4[1];
            float bf[8] = {f0.x, f0.y, f0.z, f0.w, f1.x, f1.y, f1.z, f1.w};
            __half* bb = reinterpret_cast<__half*>(bbuf[w][tl]);
            const int r = et & 7;
            const int hi = et >> 3;
            #pragma unroll
            for (int c = 0; c < 8; ++c) {
                const int s = hcol * 8 + c;
                bb[(s * 8 + r) * 2 + hi] = __float2half_rn(bf[c]);
            }
        }
        __syncwarp();

        // ---- per-thread edges / A fragments for both tiles ----
        int2 p0[2], p1[2];
        __half2 hal0[2], hah0[2], hal1[2], hah1[2];
        #pragma unroll
        for (int tl = 0; tl < 2; ++tl) {
            const int ebase = pbase + tl * 16;
            const int e0 = min(ebase + g, n_edges - 1);
            const int e1 = min(ebase + g + 8, n_edges - 1);
            p0[tl] = reinterpret_cast<const int2*>(pairs)[e0];
            p1[tl] = reinterpret_cast<const int2*>(pairs)[e1];
            const float* A0 = A + (size_t)p0[tl].y * 16;
            const float* A1 = A + (size_t)p1[tl].y * 16;
            const float2 al0 = *reinterpret_cast<const float2*>(A0 + 2 * t);
            const float2 ah0 = *reinterpret_cast<const float2*>(A0 + 8 + 2 * t);
            const float2 al1 = *reinterpret_cast<const float2*>(A1 + 2 * t);
            const float2 ah1 = *reinterpret_cast<const float2*>(A1 + 8 + 2 * t);
            hal0[tl] = __floats2half2_rn(al0.x, al0.y);
            hah0[tl] = __floats2half2_rn(ah0.x, ah0.y);
            hal1[tl] = __floats2half2_rn(al1.x, al1.y);
            hah1[tl] = __floats2half2_rn(ah1.x, ah1.y);
        }

        float d[2][8];
        #pragma unroll
        for (int tl = 0; tl < 2; ++tl)
            #pragma unroll
            for (int q = 0; q < 8; ++q) d[tl][q] = 0.f;

        #pragma unroll
        for (int s = 0; s < 17; ++s) {
            // B fragments: shared by both tiles (depend only on s, g, t)
            const __half* Wr0 = Wsm + g * 280 + s * 16 + t * 2;
            const __half* Wr1 = Wsm + (g + 8) * 280 + s * 16 + t * 2;
            const unsigned b00 = *reinterpret_cast<const unsigned*>(Wr0);
            const unsigned b01 = *reinterpret_cast<const unsigned*>(Wr0 + 8);
            const unsigned b10 = *reinterpret_cast<const unsigned*>(Wr1);
            const unsigned b11 = *reinterpret_cast<const unsigned*>(Wr1 + 8);

            #pragma unroll
            for (int tl = 0; tl < 2; ++tl) {
                __half2 bl, bh;
                if (s < 16) {
                    const __half2 b2 = bbuf[w][tl][s][g];
                    bl = __half2half2(__low2half(b2));
                    bh = __half2half2(__high2half(b2));
                } else {
                    bl = __floats2half2_rn(1.f, 1.f);      // bias row
                    bh = bl;
                }
                const unsigned a0 = hmul2u(bl, hal0[tl]);
                const unsigned a1 = hmul2u(bh, hal1[tl]);
                const unsigned a2 = hmul2u(bl, hah0[tl]);
                const unsigned a3 = hmul2u(bh, hah1[tl]);

                mma16816(d[tl][0], d[tl][1], d[tl][2], d[tl][3],
                         a0, a1, a2, a3, b00, b01);
                mma16816(d[tl][4], d[tl][5], d[tl][6], d[tl][7],
                         a0, a1, a2, a3, b10, b11);
            }
        }

        // ---- epilogue ----
        #pragma unroll
        for (int tl = 0; tl < 2; ++tl) {
            const int ebase = pbase + tl * 16;
            const int e0 = ebase + g;
            const int e1 = ebase + g + 8;
            if (e0 < n_edges) {
                float* o = out + (size_t)p0[tl].x * 16;
                red_add_v2(o + 2 * t, d[tl][0], d[tl][1]);
                red_add_v2(o + 8 + 2 * t, d[tl][4], d[tl][5]);
            }
            if (e1 < n_edges) {
                float* o = out + (size_t)p1[tl].x * 16;
                red_add_v2(o + 2 * t, d[tl][2], d[tl][3]);
                red_add_v2(o + 8 + 2 * t, d[tl][6], d[tl][7]);
            }
        }
        __syncwarp();
    }
}

extern "C" void kernel_launch(void* const* d_in, const int* in_sizes, int n_in,
                              void* d_out, int out_size) {
    const float* A     = (const float*)d_in[0];  // atom_features [n_atoms,16]
    const float* bond  = (const float*)d_in[1];  // bond_features [n_edges,16]
    const int*   pairs = (const int*)  d_in[2];  // pair_indices  [n_edges,2]
    const float* Kmat  = (const float*)d_in[3];  // kernel [16,256]
    const float* bias  = (const float*)d_in[4];  // bias [256]
    float* out = (float*)d_out;                  // [n_atoms,16]

    const int n_edges = in_sizes[2] / 2;

    cudaMemsetAsync(out, 0, (size_t)out_size * sizeof(float), 0);
    build_w<<<1, 256>>>(Kmat, bias);

    const int blocks = (n_edges + EPC - 1) / EPC;
    edge_hmma<<<blocks, NW * 32>>>(bond, pairs, A, out, n_edges);
}